// round 5
// baseline (speedup 1.0000x reference)
#include <cuda_runtime.h>
#include <math.h>

// Fully warp-local kernel: every warp redundantly computes the 3x3 matrix M
// (z = (1,cosx0,sinx0) . M . (1,cosx1,sinx1)^T) via lane-parallel shuffles,
// with no shared memory and no __syncthreads. Input loads are front-batched
// so their DRAM latency hides under the prologue arithmetic.
//
// Lane layout for U: lane = r*4 + c holds U[r][c] (complex ux/uy).
// Lanes 16..31 replicate lanes 0..15 (r wraps), harmless.

__global__ void __launch_bounds__(128, 8) qcnn_kernel(
    const float* __restrict__ inputs,   // (B, 8) row-major
    const float* __restrict__ params,   // (48,)
    float* __restrict__ out,            // (B,)
    int n)
{
    const unsigned FULL = 0xffffffffu;

    int t = blockIdx.x * blockDim.x + threadIdx.x;
    int b0 = t * 2;

    // ---- Front-batch ALL global loads (inputs + params) ----
    const float4* in4 = reinterpret_cast<const float4*>(inputs);
    float4 e0 = make_float4(0.f, 0.f, 0.f, 0.f);
    float4 e1 = e0;
    bool valid = (b0 + 1) < n;
    if (valid) {
        e0 = __ldg(in4 + 2 * b0);       // element b0:  x0=.x, x1=.y
        e1 = __ldg(in4 + 2 * b0 + 2);   // element b0+1
    }

    float P[12];
#pragma unroll
    for (int layer = 0; layer < 3; layer++) {
#pragma unroll
        for (int q = 0; q < 4; q++)
            P[layer * 4 + q] = __ldg(params + layer * 16 + q);
    }

    // ---- Warp-parallel prologue: build U (4x4 complex) ----
    int lane = threadIdx.x & 31;
    int r = (lane >> 2) & 3;
    int c = lane & 3;
    bool rb0 = (r & 1) != 0;        // qubit B bit of row
    bool rb1 = ((r >> 1) & 1) != 0; // qubit A bit of row

    float ux = (r == c) ? 1.0f : 0.0f;
    float uy = 0.0f;

#pragma unroll
    for (int layer = 0; layer < 3; layer++) {
        float ch, sh;

        // RZ(t0) on qubit A
        __sincosf(0.5f * P[layer * 4 + 0], &sh, &ch);
        {
            float py = rb1 ? sh : -sh;
            float nx = ch * ux - py * uy;
            float ny = fmaf(ch, uy, py * ux);
            ux = nx; uy = ny;
        }
        // RX(t1) on qubit B: mix with partner row (r^1) -> lane^4
        __sincosf(0.5f * P[layer * 4 + 1], &sh, &ch);
        {
            float px = __shfl_xor_sync(FULL, ux, 4);
            float py = __shfl_xor_sync(FULL, uy, 4);
            float nx = fmaf(ch, ux,  sh * py);
            float ny = fmaf(ch, uy, -sh * px);
            ux = nx; uy = ny;
        }
        // CNOT(A->B): rows with A-bit set swap B-bit (rows 2<->3)
        {
            float px = __shfl_xor_sync(FULL, ux, 4);
            float py = __shfl_xor_sync(FULL, uy, 4);
            if (rb1) { ux = px; uy = py; }
        }
        // RZ(t2) on qubit B
        __sincosf(0.5f * P[layer * 4 + 2], &sh, &ch);
        {
            float py = rb0 ? sh : -sh;
            float nx = ch * ux - py * uy;
            float ny = fmaf(ch, uy, py * ux);
            ux = nx; uy = ny;
        }
        // RX(t3) on qubit B
        __sincosf(0.5f * P[layer * 4 + 3], &sh, &ch);
        {
            float px = __shfl_xor_sync(FULL, ux, 4);
            float py = __shfl_xor_sync(FULL, uy, 4);
            float nx = fmaf(ch, ux,  sh * py);
            float ny = fmaf(ch, uy, -sh * px);
            ux = nx; uy = ny;
        }
    }

    // ---- S[k][l] = sum_m z_m Re(conj(U[m][k]) U[m][l]), z=(+1,+1,-1,-1) ----
    // lane k*4+l computes S[k][l] (k=r, l=c); lanes 16..31 replicate.
    float Sval = 0.0f;
#pragma unroll
    for (int m = 0; m < 4; m++) {
        float ax = __shfl_sync(FULL, ux, m * 4 + r);
        float ay = __shfl_sync(FULL, uy, m * 4 + r);
        float bx = __shfl_sync(FULL, ux, m * 4 + c);
        float by = __shfl_sync(FULL, uy, m * 4 + c);
        float term = fmaf(ax, bx, ay * by);
        Sval += (m < 2) ? term : -term;
    }

    // ---- Fold S (half-angle) -> M (full-angle), lane-parallel ----
    // cos^2(x/2)=(1+C)/2, sin^2=(1-C)/2, cos(x/2)sin(x/2)=S/2.
    // u-basis terms: u=0: (a,c,w) = (0,0,+.5),(1,1,+.5)
    //                u=1:            (0,0,+.5),(1,1,-.5)
    //                u=2:            (0,1,+.5),(1,0,+.5)
    const int   Atab[3][2] = { {0,1}, {0,1}, {0,1} };
    const int   Ctab[3][2] = { {0,1}, {0,1}, {1,0} };
    const float Wtab[3][2] = { {0.5f,0.5f}, {0.5f,-0.5f}, {0.5f,0.5f} };

    int mu = lane / 3;  int mv = lane - mu * 3;
    if (lane >= 9) { mu = 0; mv = 0; }  // lanes 9..31 compute a dummy (still shuffle)

    float Macc = 0.0f;
#pragma unroll
    for (int i = 0; i < 2; i++) {
#pragma unroll
        for (int j = 0; j < 2; j++) {
            int k   = 2 * Atab[mu][i] + Atab[mv][j];
            int l   = 2 * Ctab[mu][i] + Ctab[mv][j];
            float w = Wtab[mu][i] * Wtab[mv][j];
            float s = __shfl_sync(FULL, Sval, k * 4 + l);
            Macc = fmaf(w, s, Macc);
        }
    }

    // ---- Broadcast M[0..8] to all lanes ----
    float m0 = __shfl_sync(FULL, Macc, 0);
    float m1 = __shfl_sync(FULL, Macc, 1);
    float m2 = __shfl_sync(FULL, Macc, 2);
    float m3 = __shfl_sync(FULL, Macc, 3);
    float m4 = __shfl_sync(FULL, Macc, 4);
    float m5 = __shfl_sync(FULL, Macc, 5);
    float m6 = __shfl_sync(FULL, Macc, 6);
    float m7 = __shfl_sync(FULL, Macc, 7);
    float m8 = __shfl_sync(FULL, Macc, 8);

    if (!valid) return;

    // ---- Evaluate both elements ----
    float C0, S0, C1, S1;
    __sincosf(e0.x, &S0, &C0);
    __sincosf(e0.y, &S1, &C1);
    float a0 = fmaf(m2, S1, fmaf(m1, C1, m0));
    float a1 = fmaf(m5, S1, fmaf(m4, C1, m3));
    float a2 = fmaf(m8, S1, fmaf(m7, C1, m6));
    float z0 = fmaf(a2, S0, fmaf(a1, C0, a0));
    float r0 = __fdividef(1.0f, 1.0f + __expf(-z0));

    __sincosf(e1.x, &S0, &C0);
    __sincosf(e1.y, &S1, &C1);
    a0 = fmaf(m2, S1, fmaf(m1, C1, m0));
    a1 = fmaf(m5, S1, fmaf(m4, C1, m3));
    a2 = fmaf(m8, S1, fmaf(m7, C1, m6));
    float z1 = fmaf(a2, S0, fmaf(a1, C0, a0));
    float r1 = __fdividef(1.0f, 1.0f + __expf(-z1));

    reinterpret_cast<float2*>(out)[t] = make_float2(r0, r1);
}

extern "C" void kernel_launch(void* const* d_in, const int* in_sizes, int n_in,
                              void* d_out, int out_size) {
    const float* inputs = (const float*)d_in[0];
    const float* params = (const float*)d_in[1];
    float* out = (float*)d_out;

    int n = out_size;  // 131072
    int threads = 128;
    int elems_per_block = threads * 2;
    int blocks = (n + elems_per_block - 1) / elems_per_block;  // 512
    qcnn_kernel<<<blocks, threads>>>(inputs, params, out, n);
}

// round 6
// speedup vs baseline: 1.0386x; 1.0386x over previous
#include <cuda_runtime.h>
#include <math.h>

// z = (1, cos x0, sin x0) . M . (1, cos x1, sin x1)^T  per element, then sigmoid.
// M (3x3) derives from S = Re(U^dag (Z x I) U) of the pair-0 2-qubit circuit.
// Warp 0 of each block computes M lane-parallel (lane = r*4+c holds U[r][c]);
// all other warps overlap their input load + trig with the prologue.

__global__ void __launch_bounds__(256) qcnn_kernel(
    const float* __restrict__ inputs,   // (B, 8) row-major
    const float* __restrict__ params,   // (48,)
    float* __restrict__ out,            // (B,)
    int n)
{
    const unsigned FULL = 0xffffffffu;
    __shared__ float sM[9];

    int t = blockIdx.x * blockDim.x + threadIdx.x;

    // ---- Every thread: front-batch its input load (independent of M) ----
    float2 x01 = make_float2(0.f, 0.f);
    bool valid = t < n;
    if (valid) {
        // row stride = 8 floats; we need x[t][0], x[t][1]
        x01 = __ldg(reinterpret_cast<const float2*>(inputs) + t * 4);
    }

    // ---- Warp 0: lane-parallel prologue ----
    if (threadIdx.x < 32) {
        int lane = threadIdx.x;
        int r = (lane >> 2) & 3;
        int c = lane & 3;
        bool rb0 = (r & 1) != 0;        // row's qubit-B bit
        bool rb1 = ((r >> 1) & 1) != 0; // row's qubit-A bit

        // Load all 12 used params, then issue all 12 sincos up-front (pipelined MUFU).
        float sh[12], ch[12];
#pragma unroll
        for (int layer = 0; layer < 3; layer++) {
#pragma unroll
            for (int q = 0; q < 4; q++) {
                float p = __ldg(params + layer * 16 + q);
                __sincosf(0.5f * p, &sh[layer * 4 + q], &ch[layer * 4 + q]);
            }
        }

        float ux = (r == c) ? 1.0f : 0.0f;
        float uy = 0.0f;

#pragma unroll
        for (int layer = 0; layer < 3; layer++) {
            float c0 = ch[layer * 4 + 0], s0 = sh[layer * 4 + 0];
            float c1 = ch[layer * 4 + 1], s1 = sh[layer * 4 + 1];
            float c2 = ch[layer * 4 + 2], s2 = sh[layer * 4 + 2];
            float c3 = ch[layer * 4 + 3], s3 = sh[layer * 4 + 3];

            // RZ on qubit A: phase e^{-+i t/2} by row A-bit
            {
                float py = rb1 ? s0 : -s0;
                float nx = c0 * ux - py * uy;
                float ny = fmaf(c0, uy, py * ux);
                ux = nx; uy = ny;
            }
            // RX on qubit B: mix with partner row (lane^4)
            {
                float px = __shfl_xor_sync(FULL, ux, 4);
                float py = __shfl_xor_sync(FULL, uy, 4);
                float nx = fmaf(c1, ux,  s1 * py);
                float ny = fmaf(c1, uy, -s1 * px);
                ux = nx; uy = ny;
            }
            // CNOT(A->B): rows with A-bit swap B-bit (rows 2<->3)
            {
                float px = __shfl_xor_sync(FULL, ux, 4);
                float py = __shfl_xor_sync(FULL, uy, 4);
                if (rb1) { ux = px; uy = py; }
            }
            // RZ on qubit B
            {
                float py = rb0 ? s2 : -s2;
                float nx = c2 * ux - py * uy;
                float ny = fmaf(c2, uy, py * ux);
                ux = nx; uy = ny;
            }
            // RX on qubit B
            {
                float px = __shfl_xor_sync(FULL, ux, 4);
                float py = __shfl_xor_sync(FULL, uy, 4);
                float nx = fmaf(c3, ux,  s3 * py);
                float ny = fmaf(c3, uy, -s3 * px);
                ux = nx; uy = ny;
            }
        }

        // S[k][l] = sum_m z_m Re(conj(U[m][k]) U[m][l]), z=(+1,+1,-1,-1); lane k*4+l
        float Sval = 0.0f;
#pragma unroll
        for (int m = 0; m < 4; m++) {
            float ax = __shfl_sync(FULL, ux, m * 4 + r);
            float ay = __shfl_sync(FULL, uy, m * 4 + r);
            float bx = __shfl_sync(FULL, ux, m * 4 + c);
            float by = __shfl_sync(FULL, uy, m * 4 + c);
            float term = fmaf(ax, bx, ay * by);
            Sval += (m < 2) ? term : -term;
        }

        // Fold half-angle quadratic form -> full-angle bilinear form, lane-parallel.
        // cos^2(x/2)=(1+C)/2, sin^2=(1-C)/2, cos*sin=S/2.
        const int   Atab[3][2] = { {0,1}, {0,1}, {0,1} };
        const int   Ctab[3][2] = { {0,1}, {0,1}, {1,0} };
        const float Wtab[3][2] = { {0.5f,0.5f}, {0.5f,-0.5f}, {0.5f,0.5f} };

        int mu = lane / 3, mv = lane - mu * 3;
        if (lane >= 9) { mu = 0; mv = 0; }

        float Macc = 0.0f;
#pragma unroll
        for (int i = 0; i < 2; i++) {
#pragma unroll
            for (int j = 0; j < 2; j++) {
                int k   = 2 * Atab[mu][i] + Atab[mv][j];
                int l   = 2 * Ctab[mu][i] + Ctab[mv][j];
                float w = Wtab[mu][i] * Wtab[mv][j];
                float s = __shfl_sync(FULL, Sval, k * 4 + l);
                Macc = fmaf(w, s, Macc);
            }
        }
        if (lane < 9) sM[lane] = Macc;
    }

    // ---- Every thread: trig on its element, independent of M (overlaps prologue) ----
    float C0, S0, C1, S1;
    __sincosf(x01.x, &S0, &C0);
    __sincosf(x01.y, &S1, &C1);

    __syncthreads();

    if (!valid) return;

    float m0 = sM[0], m1 = sM[1], m2 = sM[2];
    float m3 = sM[3], m4 = sM[4], m5 = sM[5];
    float m6 = sM[6], m7 = sM[7], m8 = sM[8];

    float a0 = fmaf(m2, S1, fmaf(m1, C1, m0));
    float a1 = fmaf(m5, S1, fmaf(m4, C1, m3));
    float a2 = fmaf(m8, S1, fmaf(m7, C1, m6));
    float z  = fmaf(a2, S0, fmaf(a1, C0, a0));

    out[t] = __fdividef(1.0f, 1.0f + __expf(-z));
}

extern "C" void kernel_launch(void* const* d_in, const int* in_sizes, int n_in,
                              void* d_out, int out_size) {
    const float* inputs = (const float*)d_in[0];
    const float* params = (const float*)d_in[1];
    float* out = (float*)d_out;

    int n = out_size;  // 131072
    int threads = 256;
    int blocks = (n + threads - 1) / threads;  // 512
    qcnn_kernel<<<blocks, threads>>>(inputs, params, out, n);
}